// round 1
// baseline (speedup 1.0000x reference)
#include <cuda_runtime.h>
#include <cuda_bf16.h>
#include <math.h>

// Problem constants
#define T_STEPS 2048
#define H_DIM   1024
#define G_DIM   4096   // 4*H
#define NCTA    128    // scan CTAs (<= 148 SMs -> co-resident, spin barrier safe)
#define J_PER_CTA 8    // h-indices per CTA  (128*8 = 1024)

// ---------------- device scratch (static: no allocation allowed) ------------
__device__ float g_gx[(size_t)T_STEPS * G_DIM];   // 32 MB precomputed gate inputs
__device__ float g_h[2][H_DIM];                   // double-buffered hidden state
__device__ int   g_cnt[T_STEPS];                  // per-step barrier counters

// ---------------- init: reset barrier counters + h0 = 0 ---------------------
__global__ void init_kernel() {
    int i = blockIdx.x * blockDim.x + threadIdx.x;
    if (i < T_STEPS) g_cnt[i] = 0;
    if (i < H_DIM) { g_h[0][i] = 0.f; g_h[1][i] = 0.f; }
}

// ---------------- GEMM: gx[t][r] = dot(emb[tok[t]], W_ih[r]) + b ------------
// C[2048,4096] = A[2048,1024] * B[4096,1024]^T, both K-major.
// 128x128x16 tiles, 256 threads, 8x8 per-thread microtile.
__global__ void __launch_bounds__(256) gemm_gx(
    const int* __restrict__ tokens, const float* __restrict__ emb,
    const float* __restrict__ Wih,  const float* __restrict__ bih,
    const float* __restrict__ bhh)
{
    __shared__ float As[16][128];
    __shared__ float Bs[16][128];
    __shared__ int   tok[128];

    const int tid = threadIdx.x;
    const int n0  = blockIdx.x * 128;
    const int m0  = blockIdx.y * 128;

    if (tid < 128) tok[tid] = tokens[m0 + tid];
    __syncthreads();

    const int trow = tid >> 4;        // 0..15
    const int tcol = tid & 15;        // 0..15
    const int lm   = tid >> 2;        // 0..63  (loader row)
    const int lk   = (tid & 3) << 2;  // 0,4,8,12 (loader k*4)

    float acc[8][8];
#pragma unroll
    for (int i = 0; i < 8; ++i)
#pragma unroll
        for (int j = 0; j < 8; ++j) acc[i][j] = 0.f;

    for (int kt = 0; kt < H_DIM; kt += 16) {
#pragma unroll
        for (int r = 0; r < 2; ++r) {
            const int m = lm + r * 64;
            float4 v = *reinterpret_cast<const float4*>(
                emb + (size_t)tok[m] * H_DIM + kt + lk);
            As[lk + 0][m] = v.x; As[lk + 1][m] = v.y;
            As[lk + 2][m] = v.z; As[lk + 3][m] = v.w;
            float4 u = *reinterpret_cast<const float4*>(
                Wih + (size_t)(n0 + m) * H_DIM + kt + lk);
            Bs[lk + 0][m] = u.x; Bs[lk + 1][m] = u.y;
            Bs[lk + 2][m] = u.z; Bs[lk + 3][m] = u.w;
        }
        __syncthreads();

#pragma unroll
        for (int kk = 0; kk < 16; ++kk) {
            float a[8], b[8];
            float4 a0 = *reinterpret_cast<const float4*>(&As[kk][trow * 8]);
            float4 a1 = *reinterpret_cast<const float4*>(&As[kk][trow * 8 + 4]);
            float4 b0 = *reinterpret_cast<const float4*>(&Bs[kk][tcol * 8]);
            float4 b1 = *reinterpret_cast<const float4*>(&Bs[kk][tcol * 8 + 4]);
            a[0]=a0.x; a[1]=a0.y; a[2]=a0.z; a[3]=a0.w;
            a[4]=a1.x; a[5]=a1.y; a[6]=a1.z; a[7]=a1.w;
            b[0]=b0.x; b[1]=b0.y; b[2]=b0.z; b[3]=b0.w;
            b[4]=b1.x; b[5]=b1.y; b[6]=b1.z; b[7]=b1.w;
#pragma unroll
            for (int i = 0; i < 8; ++i)
#pragma unroll
                for (int j = 0; j < 8; ++j)
                    acc[i][j] = fmaf(a[i], b[j], acc[i][j]);
        }
        __syncthreads();
    }

    // epilogue: add (b_ih + b_hh)
    float bias[8];
#pragma unroll
    for (int j = 0; j < 8; ++j) {
        const int n = n0 + tcol * 8 + j;
        bias[j] = bih[n] + bhh[n];
    }
#pragma unroll
    for (int i = 0; i < 8; ++i) {
        const int m = m0 + trow * 8 + i;
        float* orow = g_gx + (size_t)m * G_DIM + n0 + tcol * 8;
#pragma unroll
        for (int j = 0; j < 8; ++j) orow[j] = acc[i][j] + bias[j];
    }
}

// ---------------- persistent LSTM scan --------------------------------------
// 128 CTAs x 1024 threads. W_hh lives in registers (32 fp32/thread).
// Thread layout: group g = tid/128 handles j = blockIdx.x*8 + g (all 4 gates),
// thread-in-group t = tid%128 covers k in [t*8, t*8+8).
__global__ void __launch_bounds__(1024, 1) lstm_scan(
    const float* __restrict__ Whh, float* __restrict__ out)
{
    const int tid  = threadIdx.x;
    const int b    = blockIdx.x;
    const int grp  = tid >> 7;        // 0..7
    const int t    = tid & 127;       // 0..127
    const int j    = (b << 3) + grp;  // 0..1023
    const int k0   = t << 3;          // 0..1016
    const int lane = tid & 31;
    const int wig  = (tid >> 5) & 3;  // warp within group

    // load W_hh slice into registers: w[gate][kk]
    float w[4][8];
#pragma unroll
    for (int gate = 0; gate < 4; ++gate) {
        const float* wr = Whh + (size_t)(gate * H_DIM + j) * H_DIM + k0;
#pragma unroll
        for (int kk = 0; kk < 8; ++kk) w[gate][kk] = wr[kk];
    }

    __shared__ float hs[H_DIM];
    __shared__ float red[J_PER_CTA][4][4];  // [group][warp][gate]

    const bool leader = (t == 0);
    float c = 0.f;

    for (int s = 0; s < T_STEPS; ++s) {
        // fetch current h (written by all CTAs last step; barrier made it visible)
        const float* hcur = g_h[s & 1];
        hs[tid] = __ldcg(hcur + tid);
        __syncthreads();

        float4 ha = *reinterpret_cast<const float4*>(hs + k0);
        float4 hb = *reinterpret_cast<const float4*>(hs + k0 + 4);
        float hv[8] = {ha.x, ha.y, ha.z, ha.w, hb.x, hb.y, hb.z, hb.w};

        float a0 = 0.f, a1 = 0.f, a2 = 0.f, a3 = 0.f;
#pragma unroll
        for (int kk = 0; kk < 8; ++kk) {
            a0 = fmaf(w[0][kk], hv[kk], a0);
            a1 = fmaf(w[1][kk], hv[kk], a1);
            a2 = fmaf(w[2][kk], hv[kk], a2);
            a3 = fmaf(w[3][kk], hv[kk], a3);
        }
#pragma unroll
        for (int off = 16; off; off >>= 1) {
            a0 += __shfl_down_sync(0xFFFFFFFFu, a0, off);
            a1 += __shfl_down_sync(0xFFFFFFFFu, a1, off);
            a2 += __shfl_down_sync(0xFFFFFFFFu, a2, off);
            a3 += __shfl_down_sync(0xFFFFFFFFu, a3, off);
        }
        if (lane == 0) {
            red[grp][wig][0] = a0; red[grp][wig][1] = a1;
            red[grp][wig][2] = a2; red[grp][wig][3] = a3;
        }
        __syncthreads();

        if (leader) {
            float gi = red[grp][0][0] + red[grp][1][0] + red[grp][2][0] + red[grp][3][0];
            float gf = red[grp][0][1] + red[grp][1][1] + red[grp][2][1] + red[grp][3][1];
            float gg = red[grp][0][2] + red[grp][1][2] + red[grp][2][2] + red[grp][3][2];
            float go = red[grp][0][3] + red[grp][1][3] + red[grp][2][3] + red[grp][3][3];
            const float* gxr = g_gx + (size_t)s * G_DIM + j;
            gi += gxr[0];
            gf += gxr[H_DIM];
            gg += gxr[2 * H_DIM];
            go += gxr[3 * H_DIM];
            gi = 1.f / (1.f + expf(-gi));
            gf = 1.f / (1.f + expf(-gf));
            gg = tanhf(gg);
            go = 1.f / (1.f + expf(-go));
            c = fmaf(gf, c, gi * gg);
            float h = go * tanhf(c);
            g_h[(s + 1) & 1][j] = h;
            if (s == T_STEPS - 1) { out[j] = h; out[H_DIM + j] = c; }
            __threadfence();  // gpu-scope: makes h store visible + orders before arrive
        }
        __syncthreads();

        // one global barrier per step (h is double-buffered)
        if (tid == 0) {
            atomicAdd(&g_cnt[s], 1);
            volatile int* p = g_cnt + s;
            while (*p != NCTA) { }
            __threadfence();  // acquire: invalidate L1 before next step's reads
        }
        __syncthreads();
    }
}

// ---------------- launcher ---------------------------------------------------
extern "C" void kernel_launch(void* const* d_in, const int* in_sizes, int n_in,
                              void* d_out, int out_size) {
    const int*   tokens = (const int*)d_in[0];
    const float* emb    = (const float*)d_in[1];
    const float* Wih    = (const float*)d_in[2];
    const float* Whh    = (const float*)d_in[3];
    const float* bih    = (const float*)d_in[4];
    const float* bhh    = (const float*)d_in[5];
    float* out = (float*)d_out;

    init_kernel<<<2, 1024>>>();

    dim3 ggrid(G_DIM / 128, T_STEPS / 128);  // 32 x 16
    gemm_gx<<<ggrid, 256>>>(tokens, emb, Wih, bih, bhh);

    lstm_scan<<<NCTA, 1024>>>(Whh, out);
}

// round 2
// speedup vs baseline: 1.3862x; 1.3862x over previous
#include <cuda_runtime.h>
#include <cuda_bf16.h>
#include <math.h>

// Problem constants
#define T_STEPS 2048
#define H_DIM   1024
#define G_DIM   4096   // 4*H
#define NCTA    128    // scan CTAs (<= SM count -> co-resident, spin barrier safe)

typedef unsigned long long ull;

// ---------------- device scratch (static: no allocation allowed) ------------
__device__ float g_gx[(size_t)T_STEPS * G_DIM];   // 32 MB precomputed gate inputs
__device__ float g_h[2][H_DIM];                   // double-buffered hidden state
__device__ int   g_cnt[T_STEPS];                  // per-step barrier counters

// packed fp32x2 FMA (Blackwell FFMA2 — only reachable via PTX)
__device__ __forceinline__ ull fma2(ull a, ull b, ull c) {
    ull d;
    asm("fma.rn.f32x2 %0, %1, %2, %3;" : "=l"(d) : "l"(a), "l"(b), "l"(c));
    return d;
}

// ---------------- init: reset barrier counters + h0 = 0 ---------------------
__global__ void init_kernel() {
    int i = blockIdx.x * blockDim.x + threadIdx.x;
    if (i < T_STEPS) g_cnt[i] = 0;
    if (i < H_DIM) { g_h[0][i] = 0.f; g_h[1][i] = 0.f; }
}

// ---------------- GEMM: gx[t][r] = dot(emb[tok[t]], W_ih[r]) + b ------------
// C[2048,4096] = A[2048,1024] * B[4096,1024]^T, both K-major.
__global__ void __launch_bounds__(256) gemm_gx(
    const int* __restrict__ tokens, const float* __restrict__ emb,
    const float* __restrict__ Wih,  const float* __restrict__ bih,
    const float* __restrict__ bhh)
{
    __shared__ float As[16][128];
    __shared__ float Bs[16][128];
    __shared__ int   tok[128];

    const int tid = threadIdx.x;
    const int n0  = blockIdx.x * 128;
    const int m0  = blockIdx.y * 128;

    if (tid < 128) tok[tid] = tokens[m0 + tid];
    __syncthreads();

    const int trow = tid >> 4;
    const int tcol = tid & 15;
    const int lm   = tid >> 2;
    const int lk   = (tid & 3) << 2;

    float acc[8][8];
#pragma unroll
    for (int i = 0; i < 8; ++i)
#pragma unroll
        for (int j = 0; j < 8; ++j) acc[i][j] = 0.f;

    for (int kt = 0; kt < H_DIM; kt += 16) {
#pragma unroll
        for (int r = 0; r < 2; ++r) {
            const int m = lm + r * 64;
            float4 v = *reinterpret_cast<const float4*>(
                emb + (size_t)tok[m] * H_DIM + kt + lk);
            As[lk + 0][m] = v.x; As[lk + 1][m] = v.y;
            As[lk + 2][m] = v.z; As[lk + 3][m] = v.w;
            float4 u = *reinterpret_cast<const float4*>(
                Wih + (size_t)(n0 + m) * H_DIM + kt + lk);
            Bs[lk + 0][m] = u.x; Bs[lk + 1][m] = u.y;
            Bs[lk + 2][m] = u.z; Bs[lk + 3][m] = u.w;
        }
        __syncthreads();

#pragma unroll
        for (int kk = 0; kk < 16; ++kk) {
            float a[8], b[8];
            float4 a0 = *reinterpret_cast<const float4*>(&As[kk][trow * 8]);
            float4 a1 = *reinterpret_cast<const float4*>(&As[kk][trow * 8 + 4]);
            float4 b0 = *reinterpret_cast<const float4*>(&Bs[kk][tcol * 8]);
            float4 b1 = *reinterpret_cast<const float4*>(&Bs[kk][tcol * 8 + 4]);
            a[0]=a0.x; a[1]=a0.y; a[2]=a0.z; a[3]=a0.w;
            a[4]=a1.x; a[5]=a1.y; a[6]=a1.z; a[7]=a1.w;
            b[0]=b0.x; b[1]=b0.y; b[2]=b0.z; b[3]=b0.w;
            b[4]=b1.x; b[5]=b1.y; b[6]=b1.z; b[7]=b1.w;
#pragma unroll
            for (int i = 0; i < 8; ++i)
#pragma unroll
                for (int j = 0; j < 8; ++j)
                    acc[i][j] = fmaf(a[i], b[j], acc[i][j]);
        }
        __syncthreads();
    }

    float bias[8];
#pragma unroll
    for (int j = 0; j < 8; ++j) {
        const int n = n0 + tcol * 8 + j;
        bias[j] = bih[n] + bhh[n];
    }
#pragma unroll
    for (int i = 0; i < 8; ++i) {
        const int m = m0 + trow * 8 + i;
        float* orow = g_gx + (size_t)m * G_DIM + n0 + tcol * 8;
#pragma unroll
        for (int j = 0; j < 8; ++j) orow[j] = acc[i][j] + bias[j];
    }
}

// ---------------- persistent LSTM scan --------------------------------------
// 128 CTAs x 512 threads, 128-reg budget (no spills).
// Thread t: gate = t>>7 (0..3), k0 = (t&127)*8. Handles all 8 local j's of its
// gate over k in [k0, k0+8) -> w = 8 rows x 4 f32x2 pairs = 64 registers.
__global__ void __launch_bounds__(512, 1) lstm_scan(
    const float* __restrict__ Whh, float* __restrict__ out)
{
    const int tid  = threadIdx.x;
    const int b    = blockIdx.x;
    const int gate = tid >> 7;        // 0..3
    const int t    = tid & 127;       // k-slot
    const int k0   = t << 3;          // 0..1016
    const int lane = tid & 31;
    const int wig  = (tid >> 5) & 3;  // warp within gate group

    // W_hh slice into registers as f32x2 pairs: w2[j][pair]
    ull w2[8][4];
#pragma unroll
    for (int j = 0; j < 8; ++j) {
        const ull* wr = reinterpret_cast<const ull*>(
            Whh + (size_t)(gate * H_DIM + (b << 3) + j) * H_DIM + k0);
#pragma unroll
        for (int p = 0; p < 4; ++p) w2[j][p] = wr[p];
    }

    __shared__ float hs[H_DIM];
    __shared__ float red[4][4][8];   // [gate][warp-in-gate][j]

    float c = 0.f;                    // only meaningful for leaders (tid<8)
    const int jg = (b << 3) + tid;    // leader's global j (tid<8)

    for (int s = 0; s < T_STEPS; ++s) {
        // leaders prefetch gx early (independent of h)
        float pgi = 0.f, pgf = 0.f, pgg = 0.f, pgo = 0.f;
        if (tid < 8) {
            const float* gxr = g_gx + (size_t)s * G_DIM + jg;
            pgi = gxr[0];
            pgf = gxr[H_DIM];
            pgg = gxr[2 * H_DIM];
            pgo = gxr[3 * H_DIM];
        }

        // fetch current h (L2, written by all CTAs last step)
        const float* hcur = g_h[s & 1];
        {
            float2 v = *reinterpret_cast<const float2*>(hcur + tid * 2);
            // force L2 path (bypass stale L1)
            float2 w_;
            asm("ld.global.cg.v2.f32 {%0,%1}, [%2];"
                : "=f"(w_.x), "=f"(w_.y) : "l"(hcur + tid * 2));
            (void)v;
            *reinterpret_cast<float2*>(hs + tid * 2) = w_;
        }
        __syncthreads();

        // h pairs for my k range
        ull h2[4];
        {
            const ull* hp = reinterpret_cast<const ull*>(hs + k0);
#pragma unroll
            for (int p = 0; p < 4; ++p) h2[p] = hp[p];
        }

        // 8 rows x 4 packed FMAs
        ull acc2[8];
#pragma unroll
        for (int j = 0; j < 8; ++j) {
            ull a = 0;
#pragma unroll
            for (int p = 0; p < 4; ++p) a = fma2(w2[j][p], h2[p], a);
            acc2[j] = a;
        }
        float acc[8];
#pragma unroll
        for (int j = 0; j < 8; ++j) {
            float2 f = *reinterpret_cast<float2*>(&acc2[j]);
            acc[j] = f.x + f.y;
        }

        // row-folding butterfly reduction: 16 shfls total
#pragma unroll
        for (int j = 0; j < 8; ++j)
            acc[j] += __shfl_xor_sync(0xFFFFFFFFu, acc[j], 16);
        float b4[4];
#pragma unroll
        for (int j = 0; j < 4; ++j) {
            b4[j] = (lane & 16) ? acc[j + 4] : acc[j];
            b4[j] += __shfl_xor_sync(0xFFFFFFFFu, b4[j], 8);
        }
        float b2[2];
#pragma unroll
        for (int j = 0; j < 2; ++j) {
            b2[j] = (lane & 8) ? b4[j + 2] : b4[j];
            b2[j] += __shfl_xor_sync(0xFFFFFFFFu, b2[j], 4);
        }
        float b1 = (lane & 4) ? b2[1] : b2[0];
        b1 += __shfl_xor_sync(0xFFFFFFFFu, b1, 2);
        b1 += __shfl_xor_sync(0xFFFFFFFFu, b1, 1);
        // lane holds total for local row (lane>>2)&7
        if ((lane & 3) == 0) red[gate][wig][(lane >> 2) & 7] = b1;
        __syncthreads();

        // leaders: final sum + activations + h/c update
        if (tid < 8) {
            const int j = tid;
            float gi = pgi + red[0][0][j] + red[0][1][j] + red[0][2][j] + red[0][3][j];
            float gf = pgf + red[1][0][j] + red[1][1][j] + red[1][2][j] + red[1][3][j];
            float gg = pgg + red[2][0][j] + red[2][1][j] + red[2][2][j] + red[2][3][j];
            float go = pgo + red[3][0][j] + red[3][1][j] + red[3][2][j] + red[3][3][j];
            gi = 1.f / (1.f + expf(-gi));
            gf = 1.f / (1.f + expf(-gf));
            gg = tanhf(gg);
            go = 1.f / (1.f + expf(-go));
            c = fmaf(gf, c, gi * gg);
            float h = go * tanhf(c);
            g_h[(s + 1) & 1][jg] = h;
            if (s == T_STEPS - 1) { out[jg] = h; out[H_DIM + jg] = c; }
            __threadfence();  // make h store gpu-visible before arrive
        }
        __syncthreads();

        // one global barrier per step (h is double-buffered)
        if (tid == 0) {
            atomicAdd(&g_cnt[s], 1);
            volatile int* p = g_cnt + s;
            while (*p != NCTA) { }
            __threadfence();  // acquire before next step's reads
        }
        __syncthreads();
    }
}

// ---------------- launcher ---------------------------------------------------
extern "C" void kernel_launch(void* const* d_in, const int* in_sizes, int n_in,
                              void* d_out, int out_size) {
    const int*   tokens = (const int*)d_in[0];
    const float* emb    = (const float*)d_in[1];
    const float* Wih    = (const float*)d_in[2];
    const float* Whh    = (const float*)d_in[3];
    const float* bih    = (const float*)d_in[4];
    const float* bhh    = (const float*)d_in[5];
    float* out = (float*)d_out;

    init_kernel<<<2, 1024>>>();

    dim3 ggrid(G_DIM / 128, T_STEPS / 128);  // 32 x 16
    gemm_gx<<<ggrid, 256>>>(tokens, emb, Wih, bih, bhh);

    lstm_scan<<<NCTA, 512>>>(Whh, out);
}

// round 4
// speedup vs baseline: 1.4932x; 1.0771x over previous
#include <cuda_runtime.h>
#include <cuda_bf16.h>
#include <math.h>

// Problem constants
#define T_STEPS 2048
#define H_DIM   1024
#define G_DIM   4096   // 4*H
#define NCTA    128    // <= SM count -> co-resident (required for dataflow scan)

typedef unsigned long long ull;

// ---------------- device scratch (static: no allocation allowed) ------------
__device__ float g_gx[(size_t)T_STEPS * G_DIM];     // 32 MB precomputed gate inputs
// per-step tagged hidden state: packet = {low: h bits, high: tag}; tag==s valid.
// buffer 0 = h0 (tag 0), buffer s (1..T) written during step s-1 with tag s.
__device__ ull g_hp[(size_t)(T_STEPS + 1) * H_DIM];

// packed fp32x2 FMA (Blackwell FFMA2 — only reachable via PTX)
__device__ __forceinline__ ull fma2(ull a, ull b, ull c) {
    ull d;
    asm("fma.rn.f32x2 %0, %1, %2, %3;" : "=l"(d) : "l"(a), "l"(b), "l"(c));
    return d;
}

// ---------------- init: invalidate all tags, set h0 -------------------------
__global__ void init_kernel() {
    size_t i = (size_t)blockIdx.x * blockDim.x + threadIdx.x;
    size_t n = (size_t)(T_STEPS + 1) * H_DIM;
    if (i < n) {
        // buffer 0: h0 = 0, tag 0 (valid). others: invalid tag.
        g_hp[i] = (i < H_DIM) ? 0ull : 0xFFFFFFFF00000000ull;
    }
}

// ---------------- GEMM: gx[t][r] = dot(emb[tok[t]], W_ih[r]) + b ------------
__global__ void __launch_bounds__(256) gemm_gx(
    const int* __restrict__ tokens, const float* __restrict__ emb,
    const float* __restrict__ Wih,  const float* __restrict__ bih,
    const float* __restrict__ bhh)
{
    __shared__ float As[16][128];
    __shared__ float Bs[16][128];
    __shared__ int   tok[128];

    const int tid = threadIdx.x;
    const int n0  = blockIdx.x * 128;
    const int m0  = blockIdx.y * 128;

    if (tid < 128) tok[tid] = tokens[m0 + tid];
    __syncthreads();

    const int trow = tid >> 4;
    const int tcol = tid & 15;
    const int lm   = tid >> 2;
    const int lk   = (tid & 3) << 2;

    float acc[8][8];
#pragma unroll
    for (int i = 0; i < 8; ++i)
#pragma unroll
        for (int j = 0; j < 8; ++j) acc[i][j] = 0.f;

    for (int kt = 0; kt < H_DIM; kt += 16) {
#pragma unroll
        for (int r = 0; r < 2; ++r) {
            const int m = lm + r * 64;
            float4 v = *reinterpret_cast<const float4*>(
                emb + (size_t)tok[m] * H_DIM + kt + lk);
            As[lk + 0][m] = v.x; As[lk + 1][m] = v.y;
            As[lk + 2][m] = v.z; As[lk + 3][m] = v.w;
            float4 u = *reinterpret_cast<const float4*>(
                Wih + (size_t)(n0 + m) * H_DIM + kt + lk);
            Bs[lk + 0][m] = u.x; Bs[lk + 1][m] = u.y;
            Bs[lk + 2][m] = u.z; Bs[lk + 3][m] = u.w;
        }
        __syncthreads();

#pragma unroll
        for (int kk = 0; kk < 16; ++kk) {
            float a[8], b[8];
            float4 a0 = *reinterpret_cast<const float4*>(&As[kk][trow * 8]);
            float4 a1 = *reinterpret_cast<const float4*>(&As[kk][trow * 8 + 4]);
            float4 b0 = *reinterpret_cast<const float4*>(&Bs[kk][tcol * 8]);
            float4 b1 = *reinterpret_cast<const float4*>(&Bs[kk][tcol * 8 + 4]);
            a[0]=a0.x; a[1]=a0.y; a[2]=a0.z; a[3]=a0.w;
            a[4]=a1.x; a[5]=a1.y; a[6]=a1.z; a[7]=a1.w;
            b[0]=b0.x; b[1]=b0.y; b[2]=b0.z; b[3]=b0.w;
            b[4]=b1.x; b[5]=b1.y; b[6]=b1.z; b[7]=b1.w;
#pragma unroll
            for (int i = 0; i < 8; ++i)
#pragma unroll
                for (int j = 0; j < 8; ++j)
                    acc[i][j] = fmaf(a[i], b[j], acc[i][j]);
        }
        __syncthreads();
    }

    float bias[8];
#pragma unroll
    for (int j = 0; j < 8; ++j) {
        const int n = n0 + tcol * 8 + j;
        bias[j] = bih[n] + bhh[n];
    }
#pragma unroll
    for (int i = 0; i < 8; ++i) {
        const int m = m0 + trow * 8 + i;
        float* orow = g_gx + (size_t)m * G_DIM + n0 + tcol * 8;
#pragma unroll
        for (int j = 0; j < 8; ++j) orow[j] = acc[i][j] + bias[j];
    }
}

// ---------------- persistent LSTM scan (barrier-free dataflow) ---------------
// 128 CTAs x 512 threads. W_hh register-resident (64 regs/thread).
// Handshake: leaders publish {h, tag=s+1} with st.release.gpu (8B atomic);
// consumers spin on ld.acquire.gpu. No tearing, no fences, no global barrier.
__global__ void __launch_bounds__(512, 1) lstm_scan(
    const float* __restrict__ Whh, float* __restrict__ out)
{
    const int tid  = threadIdx.x;
    const int b    = blockIdx.x;
    const int gate = tid >> 7;        // 0..3
    const int t    = tid & 127;       // k-slot
    const int k0   = t << 3;          // 0..1016
    const int lane = tid & 31;
    const int wig  = (tid >> 5) & 3;  // warp within gate group

    // W_hh slice into registers as f32x2 pairs: w2[j][pair]
    ull w2[8][4];
#pragma unroll
    for (int j = 0; j < 8; ++j) {
        const ull* wr = reinterpret_cast<const ull*>(
            Whh + (size_t)(gate * H_DIM + (b << 3) + j) * H_DIM + k0);
#pragma unroll
        for (int p = 0; p < 4; ++p) w2[j][p] = wr[p];
    }

    __shared__ float hs[H_DIM];
    __shared__ float red[4][4][8];   // [gate][warp-in-gate][j]

    float c = 0.f;                    // leaders only (tid<8)
    const int jg = (b << 3) + tid;    // leader's global j (tid<8)

    for (int s = 0; s < T_STEPS; ++s) {
        // leaders prefetch gx early (independent of h -> overlaps the poll)
        float pgi = 0.f, pgf = 0.f, pgg = 0.f, pgo = 0.f;
        if (tid < 8) {
            const float* gxr = g_gx + (size_t)s * G_DIM + jg;
            pgi = __ldg(gxr);
            pgf = __ldg(gxr + H_DIM);
            pgg = __ldg(gxr + 2 * H_DIM);
            pgo = __ldg(gxr + 3 * H_DIM);
        }

        // poll tagged h packets (acquire): thread owns entries 2*tid, 2*tid+1
        {
            const ull* src = g_hp + (size_t)s * H_DIM + tid * 2;
            const unsigned expd = (unsigned)s;
            ull p0, p1;
            do {
                asm volatile("ld.acquire.gpu.global.u64 %0, [%1];"
                             : "=l"(p0) : "l"(src) : "memory");
            } while ((unsigned)(p0 >> 32) != expd);
            do {
                asm volatile("ld.acquire.gpu.global.u64 %0, [%1];"
                             : "=l"(p1) : "l"(src + 1) : "memory");
            } while ((unsigned)(p1 >> 32) != expd);
            hs[tid * 2]     = __uint_as_float((unsigned)p0);
            hs[tid * 2 + 1] = __uint_as_float((unsigned)p1);
        }
        __syncthreads();

        // h pairs for my k range
        ull h2[4];
        {
            const ull* hp = reinterpret_cast<const ull*>(hs + k0);
#pragma unroll
            for (int p = 0; p < 4; ++p) h2[p] = hp[p];
        }

        // 8 rows x 4 packed FMAs
        ull acc2[8];
#pragma unroll
        for (int j = 0; j < 8; ++j) {
            ull a = 0;
#pragma unroll
            for (int p = 0; p < 4; ++p) a = fma2(w2[j][p], h2[p], a);
            acc2[j] = a;
        }
        float acc[8];
#pragma unroll
        for (int j = 0; j < 8; ++j) {
            float2 f = *reinterpret_cast<float2*>(&acc2[j]);
            acc[j] = f.x + f.y;
        }

        // row-folding butterfly reduction: 16 shfls total
#pragma unroll
        for (int j = 0; j < 8; ++j)
            acc[j] += __shfl_xor_sync(0xFFFFFFFFu, acc[j], 16);
        float b4[4];
#pragma unroll
        for (int j = 0; j < 4; ++j) {
            b4[j] = (lane & 16) ? acc[j + 4] : acc[j];
            b4[j] += __shfl_xor_sync(0xFFFFFFFFu, b4[j], 8);
        }
        float b2[2];
#pragma unroll
        for (int j = 0; j < 2; ++j) {
            b2[j] = (lane & 8) ? b4[j + 2] : b4[j];
            b2[j] += __shfl_xor_sync(0xFFFFFFFFu, b2[j], 4);
        }
        float b1 = (lane & 4) ? b2[1] : b2[0];
        b1 += __shfl_xor_sync(0xFFFFFFFFu, b1, 2);
        b1 += __shfl_xor_sync(0xFFFFFFFFu, b1, 1);
        if ((lane & 3) == 0) red[gate][wig][(lane >> 2) & 7] = b1;
        __syncthreads();

        // leaders: final sum + accurate activations + release-publish tagged h
        if (tid < 8) {
            const int j = tid;
            float gi = pgi + red[0][0][j] + red[0][1][j] + red[0][2][j] + red[0][3][j];
            float gf = pgf + red[1][0][j] + red[1][1][j] + red[1][2][j] + red[1][3][j];
            float gg = pgg + red[2][0][j] + red[2][1][j] + red[2][2][j] + red[2][3][j];
            float go = pgo + red[3][0][j] + red[3][1][j] + red[3][2][j] + red[3][3][j];
            gi = 1.f / (1.f + expf(-gi));
            gf = 1.f / (1.f + expf(-gf));
            gg = tanhf(gg);
            go = 1.f / (1.f + expf(-go));
            c = fmaf(gf, c, gi * gg);
            float h = go * tanhf(c);
            ull pkt = (ull)__float_as_uint(h) | ((ull)(unsigned)(s + 1) << 32);
            ull* dst = g_hp + (size_t)(s + 1) * H_DIM + jg;
            asm volatile("st.release.gpu.global.u64 [%0], %1;"
                         :: "l"(dst), "l"(pkt) : "memory");
            if (s == T_STEPS - 1) { out[jg] = h; out[H_DIM + jg] = c; }
        }
        // no end-of-step barrier: per-step buffers, acquire/release tags gate reads
    }
}

// ---------------- launcher ---------------------------------------------------
extern "C" void kernel_launch(void* const* d_in, const int* in_sizes, int n_in,
                              void* d_out, int out_size) {
    const int*   tokens = (const int*)d_in[0];
    const float* emb    = (const float*)d_in[1];
    const float* Wih    = (const float*)d_in[2];
    const float* Whh    = (const float*)d_in[3];
    const float* bih    = (const float*)d_in[4];
    const float* bhh    = (const float*)d_in[5];
    float* out = (float*)d_out;

    init_kernel<<<(int)(((size_t)(T_STEPS + 1) * H_DIM + 1023) / 1024), 1024>>>();

    dim3 ggrid(G_DIM / 128, T_STEPS / 128);  // 32 x 16
    gemm_gx<<<ggrid, 256>>>(tokens, emb, Wih, bih, bhh);

    lstm_scan<<<NCTA, 512>>>(Whh, out);
}